// round 12
// baseline (speedup 1.0000x reference)
#include <cuda_runtime.h>
#include <cuda_bf16.h>
#include <math.h>
#include <stdint.h>

#define BB 64
#define LL 256
#define DIN 55
#define AH 32
#define AC 8
#define CC 64
#define GG 192
#define HH 64
#define SIGW 4160   // CC + CC*CC = 65 * 64

// Scratch (device globals — no runtime allocation allowed)
__device__ float g_P[(size_t)BB * CC * LL];          // p in [b][c][t] layout, 4 MB
__device__ float g_R[(size_t)BB * LL * GG];          // per-step projection increments, 12.6 MB
__device__ uint32_t g_Wsp[(size_t)65 * GG * 64];     // W pre-split bf16 hi/lo half2, 3.2 MB

// ---------------------------------------------------------------------------
// bf16 helpers
// ---------------------------------------------------------------------------
__device__ __forceinline__ float bf_hi(float x) {
    return __bfloat162float(__float2bfloat16_rn(x));
}
__device__ __forceinline__ uint32_t bfpack(float x, float y) {
    __nv_bfloat162 t = __floats2bfloat162_rn(x, y);   // .x = x (low 16 bits)
    return *reinterpret_cast<uint32_t*>(&t);
}

// ---------------------------------------------------------------------------
// Kernel W: pre-split Wih0 into bf16 hi/lo, chunk-major, interleaved layout.
// ---------------------------------------------------------------------------
__global__ void __launch_bounds__(256) wsplit_kernel(const float* __restrict__ Wih0)
{
    int idx = blockIdx.x * 256 + threadIdx.x;       // 65*192*16 quads
    if (idx >= 65 * GG * 16) return;
    int q = idx & 15;
    int g = (idx >> 4) % GG;
    int m = (idx >> 4) / GG;
    float4 w = *(const float4*)(Wih0 + (size_t)g * SIGW + 64 * m + 4 * q);
    float hx = bf_hi(w.x), hy = bf_hi(w.y), hz = bf_hi(w.z), hw = bf_hi(w.w);
    uint32_t* o = g_Wsp + ((size_t)(m * GG + g) * 64) + 4 * q;
    o[0] = bfpack(hx, hy);
    o[1] = bfpack(w.x - hx, w.y - hy);
    o[2] = bfpack(hz, hw);
    o[3] = bfpack(w.z - hz, w.w - hw);
}

// ---------------------------------------------------------------------------
// Kernel A: Augment. p = concat(x, time, relu(x W1^T + b1) W2^T + b2)
// ---------------------------------------------------------------------------
__global__ void __launch_bounds__(LL) augment_kernel(
    const float* __restrict__ x,
    const float* __restrict__ w1, const float* __restrict__ b1,
    const float* __restrict__ w2, const float* __restrict__ b2)
{
    __shared__ float w1s[AH * DIN];
    __shared__ float w2s[AC * AH];
    __shared__ float b1s[AH];
    __shared__ float b2s[AC];

    int b = blockIdx.x;
    int t = threadIdx.x;

    for (int i = threadIdx.x; i < AH * DIN; i += blockDim.x) w1s[i] = w1[i];
    for (int i = threadIdx.x; i < AC * AH; i += blockDim.x)  w2s[i] = w2[i];
    if (threadIdx.x < AH) b1s[threadIdx.x] = b1[threadIdx.x];
    if (threadIdx.x < AC) b2s[threadIdx.x] = b2[threadIdx.x];
    __syncthreads();

    float xv[DIN];
    const float* xp = x + ((size_t)b * LL + t) * DIN;
#pragma unroll
    for (int c = 0; c < DIN; c++) xv[c] = xp[c];

    float hb[AH];
#pragma unroll
    for (int h = 0; h < AH; h++) {
        float acc = b1s[h];
#pragma unroll
        for (int c = 0; c < DIN; c++) acc += w1s[h * DIN + c] * xv[c];
        hb[h] = fmaxf(acc, 0.0f);
    }

    float* Pp = g_P + (size_t)b * CC * LL + t;   // [b][c][t]: stride LL per channel
#pragma unroll
    for (int c = 0; c < DIN; c++) Pp[(size_t)c * LL] = xv[c];
    Pp[(size_t)DIN * LL] = (float)t / (float)(LL - 1);
#pragma unroll
    for (int a = 0; a < AC; a++) {
        float acc = b2s[a];
#pragma unroll
        for (int h = 0; h < AH; h++) acc += w2s[a * AH + h] * hb[h];
        Pp[(size_t)(DIN + 1 + a) * LL] = acc;
    }
}

// ---------------------------------------------------------------------------
// MMA / cp.async helpers
// ---------------------------------------------------------------------------
#define MMA_BF16(c0, c1, c2, c3, a0, a1, a2, a3, b0, b1)                       \
    asm volatile(                                                              \
        "mma.sync.aligned.m16n8k16.row.col.f32.bf16.bf16.f32 "                 \
        "{%0,%1,%2,%3}, {%4,%5,%6,%7}, {%8,%9}, {%0,%1,%2,%3};"                \
        : "+f"(c0), "+f"(c1), "+f"(c2), "+f"(c3)                               \
        : "r"(a0), "r"(a1), "r"(a2), "r"(a3), "r"(b0), "r"(b1))

#define FMA2(d, a, b, c) \
    asm("fma.rn.f32x2 %0, %1, %2, %3;" : "=l"(d) : "l"(a), "l"(b), "l"(c))

__device__ __forceinline__ void cp_async16(uint32_t dst_smem, const void* src) {
    asm volatile("cp.async.cg.shared.global [%0], [%1], 16;"
                 :: "r"(dst_smem), "l"(src));
}
#define CP_COMMIT() asm volatile("cp.async.commit_group;")
#define CP_WAIT1()  asm volatile("cp.async.wait_group 1;" ::: "memory")

// ---------------------------------------------------------------------------
// Kernel B v3 (bf16 split TC, pre-split W + cp.async triple-buffer)
// ---------------------------------------------------------------------------
#define PADH 36
#define GT 96
#define WROW 72
#define WBUF_WORDS (GT * WROW)
#define SM_A_OFF   0
#define SM_DH_OFF  (64 * 68)
#define SM_DL_OFF  (SM_DH_OFF + 64 * PADH)
#define SM_W_OFF   (SM_DL_OFF + 64 * PADH)
#define SMEM_TC_WORDS (SM_W_OFF + 3 * WBUF_WORDS)
#define SMEM_TC_BYTES (SMEM_TC_WORDS * 4)    // 118784 B

__global__ void __launch_bounds__(256) siggemm_bf16_kernel()
{
    extern __shared__ uint32_t smw[];
    float*    a_s  = (float*)smw;
    uint32_t* Dh2  = smw + SM_DH_OFF;
    uint32_t* Dl2  = smw + SM_DL_OFF;
    uint32_t* Wbuf = smw + SM_W_OFF;

    const uint32_t sbase = (uint32_t)__cvta_generic_to_shared(smw);

    const int ptile = blockIdx.x;
    const int gbase = blockIdx.y * GT;
    const int b  = ptile >> 2;
    const int t0 = (ptile & 3) * 64;
    const int tid  = threadIdx.x;
    const int warp = tid >> 5;
    const int lane = tid & 31;
    const int warpM = warp & 1;
    const int warpN = warp >> 1;
    const int lq = lane >> 2;
    const int lr = lane & 3;

    int cp_dst[6];
    size_t cp_src[6];
#pragma unroll
    for (int k = 0; k < 6; k++) {
        int idx = tid + k * 256;
        int gg  = idx >> 4;
        int qq  = idx & 15;
        cp_dst[k] = (gg * WROW + 4 * qq) * 4;
        cp_src[k] = (size_t)(gbase + gg) * 64 + 4 * qq;
    }

    {
        uint32_t wb0 = sbase + (SM_W_OFF + 0 * WBUF_WORDS) * 4;
#pragma unroll
        for (int k = 0; k < 6; k++)
            cp_async16(wb0 + cp_dst[k], g_Wsp + cp_src[k]);
        CP_COMMIT();
        uint32_t wb1 = sbase + (SM_W_OFF + 1 * WBUF_WORDS) * 4;
        const uint32_t* src1 = g_Wsp + (size_t)GG * 64;
#pragma unroll
        for (int k = 0; k < 6; k++)
            cp_async16(wb1 + cp_dst[k], src1 + cp_src[k]);
        CP_COMMIT();
    }

    {
        const float* Pb = g_P + (size_t)b * CC * LL;
        for (int idx = tid; idx < 64 * 32; idx += 256) {
            int j2 = idx >> 6;
            int p  = idx & 63;
            int t  = t0 + p;
            const float* Pc0 = Pb + (size_t)(2 * j2) * LL;
            const float* Pc1 = Pc0 + LL;
            float c0 = Pc0[t], p0 = (t == 0) ? 0.0f : Pc0[t - 1];
            float c1 = Pc1[t], p1 = (t == 0) ? 0.0f : Pc1[t - 1];
            float d0 = c0 - p0, d1 = c1 - p1;
            a_s[(2 * j2) * 68 + p]     = 0.5f * (c0 + p0);
            a_s[(2 * j2 + 1) * 68 + p] = 0.5f * (c1 + p1);
            float h0 = bf_hi(d0), h1 = bf_hi(d1);
            Dh2[p * PADH + j2] = bfpack(h0, h1);
            Dl2[p * PADH + j2] = bfpack(d0 - h0, d1 - h1);
        }
    }
    __syncthreads();

    uint32_t Ah[2][4][4], Al[2][4][4];
#pragma unroll
    for (int mf = 0; mf < 2; mf++) {
        int r0 = (warpM * 32 + mf * 16 + lq) * PADH;
        int r1 = (warpM * 32 + mf * 16 + 8 + lq) * PADH;
#pragma unroll
        for (int ks = 0; ks < 4; ks++) {
            int c0 = 8 * ks + lr, c1 = 8 * ks + 4 + lr;
            Ah[mf][ks][0] = Dh2[r0 + c0];
            Ah[mf][ks][1] = Dh2[r1 + c0];
            Ah[mf][ks][2] = Dh2[r0 + c1];
            Ah[mf][ks][3] = Dh2[r1 + c1];
            Al[mf][ks][0] = Dl2[r0 + c0];
            Al[mf][ks][1] = Dl2[r1 + c0];
            Al[mf][ks][2] = Dl2[r0 + c1];
            Al[mf][ks][3] = Dl2[r1 + c1];
        }
    }

    float R[2][3][4];
#pragma unroll
    for (int mf = 0; mf < 2; mf++)
#pragma unroll
        for (int nf = 0; nf < 3; nf++)
#pragma unroll
            for (int q = 0; q < 4; q++) R[mf][nf][q] = 0.0f;

    int bufc = 0;
    for (int c = 0; c < 65; c++) {
        CP_WAIT1();
        __syncthreads();

        if (c + 2 < 65) {
            int bufn = bufc >= 1 ? bufc - 1 : 2;
            uint32_t wbn = sbase + (SM_W_OFF + bufn * WBUF_WORDS) * 4;
            const uint32_t* srcn = g_Wsp + (size_t)(c + 2) * GG * 64;
#pragma unroll
            for (int k = 0; k < 6; k++)
                cp_async16(wbn + cp_dst[k], srcn + cp_src[k]);
        }
        CP_COMMIT();

        const uint32_t* WB = Wbuf + bufc * WBUF_WORDS;

        float Y[2][3][4];
#pragma unroll
        for (int mf = 0; mf < 2; mf++)
#pragma unroll
            for (int nf = 0; nf < 3; nf++)
#pragma unroll
                for (int q = 0; q < 4; q++) Y[mf][nf][q] = 0.0f;

#pragma unroll
        for (int ks = 0; ks < 4; ks++) {
#pragma unroll
            for (int nf = 0; nf < 3; nf++) {
                int n0 = (warpN * 24 + nf * 8 + lq) * WROW;
                uint2 p0 = *(const uint2*)&WB[n0 + 2 * (8 * ks + lr)];
                uint2 p1 = *(const uint2*)&WB[n0 + 2 * (8 * ks + 4 + lr)];
#pragma unroll
                for (int mf = 0; mf < 2; mf++) {
                    MMA_BF16(Y[mf][nf][0], Y[mf][nf][1], Y[mf][nf][2], Y[mf][nf][3],
                             Ah[mf][ks][0], Ah[mf][ks][1], Ah[mf][ks][2], Ah[mf][ks][3],
                             p0.x, p1.x);
                    MMA_BF16(Y[mf][nf][0], Y[mf][nf][1], Y[mf][nf][2], Y[mf][nf][3],
                             Al[mf][ks][0], Al[mf][ks][1], Al[mf][ks][2], Al[mf][ks][3],
                             p0.x, p1.x);
                    MMA_BF16(Y[mf][nf][0], Y[mf][nf][1], Y[mf][nf][2], Y[mf][nf][3],
                             Ah[mf][ks][0], Ah[mf][ks][1], Ah[mf][ks][2], Ah[mf][ks][3],
                             p0.y, p1.y);
                }
            }
        }

#pragma unroll
        for (int mf = 0; mf < 2; mf++) {
            float av0 = 1.0f, av1 = 1.0f;
            if (c > 0) {
                int r0 = warpM * 32 + mf * 16 + lq;
                av0 = a_s[(c - 1) * 68 + r0];
                av1 = a_s[(c - 1) * 68 + r0 + 8];
            }
#pragma unroll
            for (int nf = 0; nf < 3; nf++) {
                R[mf][nf][0] = fmaf(av0, Y[mf][nf][0], R[mf][nf][0]);
                R[mf][nf][1] = fmaf(av0, Y[mf][nf][1], R[mf][nf][1]);
                R[mf][nf][2] = fmaf(av1, Y[mf][nf][2], R[mf][nf][2]);
                R[mf][nf][3] = fmaf(av1, Y[mf][nf][3], R[mf][nf][3]);
            }
        }

        bufc = (bufc == 2) ? 0 : bufc + 1;
    }

#pragma unroll
    for (int mf = 0; mf < 2; mf++) {
        int trow = t0 + warpM * 32 + mf * 16 + lq;
#pragma unroll
        for (int nf = 0; nf < 3; nf++) {
            int g = gbase + warpN * 24 + nf * 8 + 2 * lr;
            float* rp0 = g_R + ((size_t)b * LL + trow) * GG + g;
            float* rp1 = g_R + ((size_t)b * LL + trow + 8) * GG + g;
            *(float2*)rp0 = make_float2(R[mf][nf][0], R[mf][nf][1]);
            *(float2*)rp1 = make_float2(R[mf][nf][2], R[mf][nf][3]);
        }
    }
}

// ---------------------------------------------------------------------------
// Fast activations
// ---------------------------------------------------------------------------
__device__ __forceinline__ float fast_sigm(float v) {
    return __fdividef(1.0f, 1.0f + __expf(-v));
}
__device__ __forceinline__ float fast_tanh(float v) {
    v = fminf(fmaxf(v, -10.0f), 10.0f);
    float e = __expf(2.0f * v);
    return __fdividef(e - 1.0f, e + 1.0f);
}

// Half-dot (32 h values) for 3 gates; weights are 16 u64 per gate.
__device__ __forceinline__ void dot3h(const unsigned long long* __restrict__ wr,
                                      const unsigned long long* __restrict__ wz,
                                      const unsigned long long* __restrict__ wn,
                                      const float* __restrict__ hs,   // &h[32*half]
                                      float& dr, float& dz, float& dn) {
    unsigned long long sr = 0ull, sz = 0ull, sn = 0ull;
#pragma unroll
    for (int j = 0; j < 8; j++) {
        ulonglong2 h2 = *(const ulonglong2*)&hs[4 * j];
        FMA2(sr, wr[2 * j],     h2.x, sr);
        FMA2(sr, wr[2 * j + 1], h2.y, sr);
        FMA2(sz, wz[2 * j],     h2.x, sz);
        FMA2(sz, wz[2 * j + 1], h2.y, sz);
        FMA2(sn, wn[2 * j],     h2.x, sn);
        FMA2(sn, wn[2 * j + 1], h2.y, sn);
    }
    float2 a = *(float2*)&sr; dr = a.x + a.y;
    float2 b = *(float2*)&sz; dz = b.x + b.y;
    float2 c = *(float2*)&sn; dn = c.x + c.y;
}

// ---------------------------------------------------------------------------
// Kernel C v3: fused 2-layer GRU, lane-pair split dots (384 thr, 12 warps).
// 3 groups of 128 threads; lane pair (2u, 2u+1) shares hidden unit u, each
// lane holds HALF of each gate row (48 u64 regs) -> no spills; every SMSP
// carries exactly one warp of each role.
//   grp 0 (warps 0-3 ): L0 gh dots + act + r-cumsum -> h0
//   grp 1 (warps 4-7 ): L1 act(s-2) + gh1 dots(s-1) on h1
//   grp 2 (warps 8-11): L1 xg dots(s-1) from h0[s-1]
// ---------------------------------------------------------------------------
__global__ void __launch_bounds__(384, 1) gru_fused3_kernel(
    const float* __restrict__ Whh0, const float* __restrict__ bih0, const float* __restrict__ bhh0,
    const float* __restrict__ Wih1, const float* __restrict__ Whh1,
    const float* __restrict__ bih1, const float* __restrict__ bhh1,
    float* __restrict__ out)
{
    __shared__ float h0buf[2][HH];
    __shared__ float h1s[HH];
    __shared__ float xg1buf[2][3 * HH];

    const int b    = blockIdx.x;
    const int tid  = threadIdx.x;
    const int grp  = tid / 128;        // 0=L0, 1=L1g, 2=L1x
    const int gt   = tid - grp * 128;
    const int u    = gt >> 1;          // hidden unit 0..63
    const int half = gt & 1;           // which half of the 64-dot
    const int hoff = half * 32;

    const float* wsrc = (grp == 0) ? Whh0 : (grp == 1) ? Whh1 : Wih1;
    unsigned long long wr[16], wz[16], wn[16];
#pragma unroll
    for (int i = 0; i < 16; i++) {
        *(float2*)&wr[i] = *(const float2*)&wsrc[(size_t)u * HH + hoff + 2 * i];
        *(float2*)&wz[i] = *(const float2*)&wsrc[(size_t)(64 + u) * HH + hoff + 2 * i];
        *(float2*)&wn[i] = *(const float2*)&wsrc[(size_t)(128 + u) * HH + hoff + 2 * i];
    }

    float br, bz, bn;
    if (grp == 0)      { br = bhh0[u]; bz = bhh0[64 + u]; bn = bhh0[128 + u]; }
    else if (grp == 1) { br = bhh1[u]; bz = bhh1[64 + u]; bn = bhh1[128 + u]; }
    else               { br = bih1[u]; bz = bih1[64 + u]; bn = bih1[128 + u]; }

    // L0 cumsum state + r prefetch (half 0 owns)
    const float* rptr = g_R + (size_t)b * LL * GG;
    float accr = 0.f, accz = 0.f, accn = 0.f;
    float rvr = 0.f, rvz = 0.f, rvn = 0.f;
    if (grp == 0 && half == 0) {
        accr = bih0[u]; accz = bih0[64 + u]; accn = bih0[128 + u];
        rvr = rptr[u]; rvz = rptr[64 + u]; rvn = rptr[128 + u];
    }

    // L1 recurrent gate sums (combined; valid on half 0)
    float ghr = 0.f, ghz = 0.f, ghn = 0.f;

    if (tid < HH) { h0buf[0][tid] = 0.0f; h0buf[1][tid] = 0.0f; h1s[tid] = 0.0f; }
    __syncthreads();

    for (int s = 0; s <= LL + 1; s++) {
        if (grp == 0) {
            if (s < LL) {
                const float* hp = h0buf[(s + 1) & 1];   // h0[s-1]
                float pr, pz, pn;
                dot3h(wr, wz, wn, hp + hoff, pr, pz, pn);
                pr += __shfl_xor_sync(0xFFFFFFFF, pr, 1);
                pz += __shfl_xor_sync(0xFFFFFFFF, pz, 1);
                pn += __shfl_xor_sync(0xFFFFFFFF, pn, 1);
                if (half == 0) {
                    accr += rvr; accz += rvz; accn += rvn;
                    if (s + 1 < LL) {
                        const float* rn = rptr + (size_t)(s + 1) * GG;
                        rvr = rn[u]; rvz = rn[64 + u]; rvn = rn[128 + u];
                    }
                    float r = fast_sigm(accr + br + pr);
                    float z = fast_sigm(accz + bz + pz);
                    float n = fast_tanh(accn + r * (bn + pn));
                    h0buf[s & 1][u] = (1.0f - z) * n + z * hp[u];
                }
            }
        } else if (grp == 1) {
            if (s >= 2 && s <= LL + 1 && half == 0) {
                int t2 = s - 2;
                const float* xg = xg1buf[t2 & 1];
                float r = fast_sigm(xg[u] + br + ghr);
                float z = fast_sigm(xg[64 + u] + bz + ghz);
                float n = fast_tanh(xg[128 + u] + r * (bn + ghn));
                float hn2 = (1.0f - z) * n + z * h1s[u];
                h1s[u] = hn2;
                out[((size_t)b * LL + t2) * HH + u] = hn2;
            }
            if (s >= 1) {
                asm volatile("bar.sync 1, 128;" ::: "memory");  // h1 write -> dot read
                if (s <= LL) {
                    float pr, pz, pn;
                    dot3h(wr, wz, wn, h1s + hoff, pr, pz, pn);
                    ghr = pr + __shfl_xor_sync(0xFFFFFFFF, pr, 1);
                    ghz = pz + __shfl_xor_sync(0xFFFFFFFF, pz, 1);
                    ghn = pn + __shfl_xor_sync(0xFFFFFFFF, pn, 1);
                }
            }
        } else {
            if (s >= 1 && s <= LL) {
                int t = s - 1;
                const float* hp0 = h0buf[t & 1];
                float pr, pz, pn;
                dot3h(wr, wz, wn, hp0 + hoff, pr, pz, pn);
                pr += __shfl_xor_sync(0xFFFFFFFF, pr, 1);
                pz += __shfl_xor_sync(0xFFFFFFFF, pz, 1);
                pn += __shfl_xor_sync(0xFFFFFFFF, pn, 1);
                if (half == 0) {
                    float* xg = xg1buf[t & 1];
                    xg[u]        = br + pr;
                    xg[64 + u]   = bz + pz;
                    xg[128 + u]  = bn + pn;
                }
            }
        }
        __syncthreads();
    }
}

// ---------------------------------------------------------------------------
extern "C" void kernel_launch(void* const* d_in, const int* in_sizes, int n_in,
                              void* d_out, int out_size)
{
    const float* x    = (const float*)d_in[0];
    const float* cw1  = (const float*)d_in[1];
    const float* cb1  = (const float*)d_in[2];
    const float* cw2  = (const float*)d_in[3];
    const float* cb2  = (const float*)d_in[4];
    const float* Wih0 = (const float*)d_in[5];
    const float* Whh0 = (const float*)d_in[6];
    const float* bih0 = (const float*)d_in[7];
    const float* bhh0 = (const float*)d_in[8];
    const float* Wih1 = (const float*)d_in[9];
    const float* Whh1 = (const float*)d_in[10];
    const float* bih1 = (const float*)d_in[11];
    const float* bhh1 = (const float*)d_in[12];
    float* out = (float*)d_out;

    cudaFuncSetAttribute(siggemm_bf16_kernel,
                         cudaFuncAttributeMaxDynamicSharedMemorySize, SMEM_TC_BYTES);

    wsplit_kernel<<<(65 * GG * 16 + 255) / 256, 256>>>(Wih0);

    augment_kernel<<<BB, LL>>>(x, cw1, cb1, cw2, cb2);

    dim3 gridB(256, 2);
    siggemm_bf16_kernel<<<gridB, 256, SMEM_TC_BYTES>>>();

    gru_fused3_kernel<<<BB, 384>>>(Whh0, bih0, bhh0,
                                   Wih1, Whh1, bih1, bhh1, out);
}

// round 14
// speedup vs baseline: 1.2051x; 1.2051x over previous
#include <cuda_runtime.h>
#include <cuda_bf16.h>
#include <math.h>
#include <stdint.h>

#define BB 64
#define LL 256
#define DIN 55
#define AH 32
#define AC 8
#define CC 64
#define GG 192
#define HH 64
#define SIGW 4160   // CC + CC*CC = 65 * 64

// Scratch (device globals — no runtime allocation allowed)
__device__ float g_P[(size_t)BB * CC * LL];          // p in [b][c][t] layout, 4 MB
__device__ float g_R[(size_t)BB * LL * GG];          // per-step projection increments, 12.6 MB
__device__ uint32_t g_Wsp[(size_t)65 * GG * 64];     // W pre-split bf16 hi/lo half2, 3.2 MB

// ---------------------------------------------------------------------------
// bf16 helpers
// ---------------------------------------------------------------------------
__device__ __forceinline__ float bf_hi(float x) {
    return __bfloat162float(__float2bfloat16_rn(x));
}
__device__ __forceinline__ uint32_t bfpack(float x, float y) {
    __nv_bfloat162 t = __floats2bfloat162_rn(x, y);   // .x = x (low 16 bits)
    return *reinterpret_cast<uint32_t*>(&t);
}

// ---------------------------------------------------------------------------
// Kernel W: pre-split Wih0 into bf16 hi/lo, chunk-major, interleaved layout.
// ---------------------------------------------------------------------------
__global__ void __launch_bounds__(256) wsplit_kernel(const float* __restrict__ Wih0)
{
    int idx = blockIdx.x * 256 + threadIdx.x;       // 65*192*16 quads
    if (idx >= 65 * GG * 16) return;
    int q = idx & 15;
    int g = (idx >> 4) % GG;
    int m = (idx >> 4) / GG;
    float4 w = *(const float4*)(Wih0 + (size_t)g * SIGW + 64 * m + 4 * q);
    float hx = bf_hi(w.x), hy = bf_hi(w.y), hz = bf_hi(w.z), hw = bf_hi(w.w);
    uint32_t* o = g_Wsp + ((size_t)(m * GG + g) * 64) + 4 * q;
    o[0] = bfpack(hx, hy);
    o[1] = bfpack(w.x - hx, w.y - hy);
    o[2] = bfpack(hz, hw);
    o[3] = bfpack(w.z - hz, w.w - hw);
}

// ---------------------------------------------------------------------------
// Kernel A: Augment. p = concat(x, time, relu(x W1^T + b1) W2^T + b2)
// ---------------------------------------------------------------------------
__global__ void __launch_bounds__(LL) augment_kernel(
    const float* __restrict__ x,
    const float* __restrict__ w1, const float* __restrict__ b1,
    const float* __restrict__ w2, const float* __restrict__ b2)
{
    __shared__ float w1s[AH * DIN];
    __shared__ float w2s[AC * AH];
    __shared__ float b1s[AH];
    __shared__ float b2s[AC];

    int b = blockIdx.x;
    int t = threadIdx.x;

    for (int i = threadIdx.x; i < AH * DIN; i += blockDim.x) w1s[i] = w1[i];
    for (int i = threadIdx.x; i < AC * AH; i += blockDim.x)  w2s[i] = w2[i];
    if (threadIdx.x < AH) b1s[threadIdx.x] = b1[threadIdx.x];
    if (threadIdx.x < AC) b2s[threadIdx.x] = b2[threadIdx.x];
    __syncthreads();

    float xv[DIN];
    const float* xp = x + ((size_t)b * LL + t) * DIN;
#pragma unroll
    for (int c = 0; c < DIN; c++) xv[c] = xp[c];

    float hb[AH];
#pragma unroll
    for (int h = 0; h < AH; h++) {
        float acc = b1s[h];
#pragma unroll
        for (int c = 0; c < DIN; c++) acc += w1s[h * DIN + c] * xv[c];
        hb[h] = fmaxf(acc, 0.0f);
    }

    float* Pp = g_P + (size_t)b * CC * LL + t;   // [b][c][t]: stride LL per channel
#pragma unroll
    for (int c = 0; c < DIN; c++) Pp[(size_t)c * LL] = xv[c];
    Pp[(size_t)DIN * LL] = (float)t / (float)(LL - 1);
#pragma unroll
    for (int a = 0; a < AC; a++) {
        float acc = b2s[a];
#pragma unroll
        for (int h = 0; h < AH; h++) acc += w2s[a * AH + h] * hb[h];
        Pp[(size_t)(DIN + 1 + a) * LL] = acc;
    }
}

// ---------------------------------------------------------------------------
// MMA / cp.async helpers
// ---------------------------------------------------------------------------
#define MMA_BF16(c0, c1, c2, c3, a0, a1, a2, a3, b0, b1)                       \
    asm volatile(                                                              \
        "mma.sync.aligned.m16n8k16.row.col.f32.bf16.bf16.f32 "                 \
        "{%0,%1,%2,%3}, {%4,%5,%6,%7}, {%8,%9}, {%0,%1,%2,%3};"                \
        : "+f"(c0), "+f"(c1), "+f"(c2), "+f"(c3)                               \
        : "r"(a0), "r"(a1), "r"(a2), "r"(a3), "r"(b0), "r"(b1))

#define FMA2(d, a, b, c) \
    asm("fma.rn.f32x2 %0, %1, %2, %3;" : "=l"(d) : "l"(a), "l"(b), "l"(c))

__device__ __forceinline__ void cp_async16(uint32_t dst_smem, const void* src) {
    asm volatile("cp.async.cg.shared.global [%0], [%1], 16;"
                 :: "r"(dst_smem), "l"(src));
}
#define CP_COMMIT() asm volatile("cp.async.commit_group;")
#define CP_WAIT0()  asm volatile("cp.async.wait_group 0;" ::: "memory")

// ---------------------------------------------------------------------------
// Kernel B v4 (bf16 split TC, double-buffered W, 2 blocks/SM):
//   R[p,g] = sum_m scale_m[p] * (D W_m^T)[p,g],  scale_0 = 1, scale_m = a_{m-1}
// 8 warps as 4 M-warps x 2 N-warps (16 rows x 48 gates per warp).
// A fragments (D hi/lo) chunk-invariant in registers; W via cp.async.
// smem 91136 B -> 2 blocks/SM; __launch_bounds__(256,2) caps regs at 128.
// ---------------------------------------------------------------------------
#define PADH 36
#define GT 96
#define WROW 72
#define WBUF_WORDS (GT * WROW)               // 6912 words
#define SM_DH_OFF  (64 * 68)                 // after a_s
#define SM_DL_OFF  (SM_DH_OFF + 64 * PADH)
#define SM_W_OFF   (SM_DL_OFF + 64 * PADH)   // 8960 words
#define SMEM_TC_WORDS (SM_W_OFF + 2 * WBUF_WORDS)
#define SMEM_TC_BYTES (SMEM_TC_WORDS * 4)    // 91136 B

__global__ void __launch_bounds__(256, 2) siggemm_bf16_kernel()
{
    extern __shared__ uint32_t smw[];
    float*    a_s  = (float*)smw;
    uint32_t* Dh2  = smw + SM_DH_OFF;
    uint32_t* Dl2  = smw + SM_DL_OFF;
    uint32_t* Wbuf = smw + SM_W_OFF;

    const uint32_t sbase = (uint32_t)__cvta_generic_to_shared(smw);

    const int ptile = blockIdx.x;
    const int gbase = blockIdx.y * GT;
    const int b  = ptile >> 2;
    const int t0 = (ptile & 3) * 64;
    const int tid  = threadIdx.x;
    const int warp = tid >> 5;
    const int lane = tid & 31;
    const int warpM = warp & 3;              // rows 16*warpM..+15
    const int warpN = warp >> 2;             // gates 48*warpN..+47
    const int lq = lane >> 2;
    const int lr = lane & 3;

    // affine cp.async slots: k=0..5, gate gg0+16k, quad qq (const)
    const int gg0 = tid >> 4;
    const int qq  = tid & 15;
    const uint32_t cp_dst0 = sbase + (SM_W_OFF + gg0 * WROW + 4 * qq) * 4;
    const size_t   cp_src0 = (size_t)(gbase + gg0) * 64 + 4 * qq;

    // ---- issue chunk 0 into buf0 (overlaps a/D staging)
    {
#pragma unroll
        for (int k = 0; k < 6; k++)
            cp_async16(cp_dst0 + (uint32_t)(16 * WROW * 4) * k,
                       g_Wsp + cp_src0 + 1024 * k);
        CP_COMMIT();
    }

    // ---- stage a (fp32) and D (bf16 hi/lo half2 pairs)
    {
        const float* Pb = g_P + (size_t)b * CC * LL;
        for (int idx = tid; idx < 64 * 32; idx += 256) {
            int j2 = idx >> 6;
            int p  = idx & 63;
            int t  = t0 + p;
            const float* Pc0 = Pb + (size_t)(2 * j2) * LL;
            const float* Pc1 = Pc0 + LL;
            float c0 = Pc0[t], p0 = (t == 0) ? 0.0f : Pc0[t - 1];
            float c1 = Pc1[t], p1 = (t == 0) ? 0.0f : Pc1[t - 1];
            float d0 = c0 - p0, d1 = c1 - p1;
            a_s[(2 * j2) * 68 + p]     = 0.5f * (c0 + p0);
            a_s[(2 * j2 + 1) * 68 + p] = 0.5f * (c1 + p1);
            float h0 = bf_hi(d0), h1 = bf_hi(d1);
            Dh2[p * PADH + j2] = bfpack(h0, h1);
            Dl2[p * PADH + j2] = bfpack(d0 - h0, d1 - h1);
        }
    }
    __syncthreads();

    // ---- chunk-invariant A fragments (16 rows per warp)
    uint32_t Ah[4][4], Al[4][4];
    {
        int r0 = (warpM * 16 + lq) * PADH;
        int r1 = (warpM * 16 + 8 + lq) * PADH;
#pragma unroll
        for (int ks = 0; ks < 4; ks++) {
            int c0 = 8 * ks + lr, c1 = 8 * ks + 4 + lr;
            Ah[ks][0] = Dh2[r0 + c0];
            Ah[ks][1] = Dh2[r1 + c0];
            Ah[ks][2] = Dh2[r0 + c1];
            Ah[ks][3] = Dh2[r1 + c1];
            Al[ks][0] = Dl2[r0 + c0];
            Al[ks][1] = Dl2[r1 + c0];
            Al[ks][2] = Dl2[r0 + c1];
            Al[ks][3] = Dl2[r1 + c1];
        }
    }

    float R[6][4];
#pragma unroll
    for (int nf = 0; nf < 6; nf++)
#pragma unroll
        for (int q = 0; q < 4; q++) R[nf][q] = 0.0f;

    for (int c = 0; c < 65; c++) {
        CP_WAIT0();                          // chunk c landed
        __syncthreads();                     // all warps done with buf (c-1)&1

        // issue chunk c+1 into the other buffer
        if (c + 1 < 65) {
            uint32_t dstb = cp_dst0 + (uint32_t)(((c + 1) & 1) * WBUF_WORDS) * 4;
            const uint32_t* srcn = g_Wsp + (size_t)(c + 1) * GG * 64 + cp_src0;
#pragma unroll
            for (int k = 0; k < 6; k++)
                cp_async16(dstb + (uint32_t)(16 * WROW * 4) * k, srcn + 1024 * k);
        }
        CP_COMMIT();

        const uint32_t* WB = Wbuf + (c & 1) * WBUF_WORDS;

        float Y[6][4];
#pragma unroll
        for (int nf = 0; nf < 6; nf++)
#pragma unroll
            for (int q = 0; q < 4; q++) Y[nf][q] = 0.0f;

#pragma unroll
        for (int ks = 0; ks < 4; ks++) {
#pragma unroll
            for (int nf = 0; nf < 6; nf++) {
                int n0 = (warpN * 48 + nf * 8 + lq) * WROW;
                uint2 p0 = *(const uint2*)&WB[n0 + 2 * (8 * ks + lr)];
                uint2 p1 = *(const uint2*)&WB[n0 + 2 * (8 * ks + 4 + lr)];
                MMA_BF16(Y[nf][0], Y[nf][1], Y[nf][2], Y[nf][3],
                         Ah[ks][0], Ah[ks][1], Ah[ks][2], Ah[ks][3], p0.x, p1.x);
                MMA_BF16(Y[nf][0], Y[nf][1], Y[nf][2], Y[nf][3],
                         Al[ks][0], Al[ks][1], Al[ks][2], Al[ks][3], p0.x, p1.x);
                MMA_BF16(Y[nf][0], Y[nf][1], Y[nf][2], Y[nf][3],
                         Ah[ks][0], Ah[ks][1], Ah[ks][2], Ah[ks][3], p0.y, p1.y);
            }
        }

        // R += diag(scale) . Y
        float av0 = 1.0f, av1 = 1.0f;
        if (c > 0) {
            int r0 = warpM * 16 + lq;
            av0 = a_s[(c - 1) * 68 + r0];
            av1 = a_s[(c - 1) * 68 + r0 + 8];
        }
#pragma unroll
        for (int nf = 0; nf < 6; nf++) {
            R[nf][0] = fmaf(av0, Y[nf][0], R[nf][0]);
            R[nf][1] = fmaf(av0, Y[nf][1], R[nf][1]);
            R[nf][2] = fmaf(av1, Y[nf][2], R[nf][2]);
            R[nf][3] = fmaf(av1, Y[nf][3], R[nf][3]);
        }
    }

    // ---- epilogue
    {
        int trow = t0 + warpM * 16 + lq;
#pragma unroll
        for (int nf = 0; nf < 6; nf++) {
            int g = gbase + warpN * 48 + nf * 8 + 2 * lr;
            float* rp0 = g_R + ((size_t)b * LL + trow) * GG + g;
            float* rp1 = g_R + ((size_t)b * LL + trow + 8) * GG + g;
            *(float2*)rp0 = make_float2(R[nf][0], R[nf][1]);
            *(float2*)rp1 = make_float2(R[nf][2], R[nf][3]);
        }
    }
}

// ---------------------------------------------------------------------------
// Fast activations
// ---------------------------------------------------------------------------
__device__ __forceinline__ float fast_sigm(float v) {
    return __fdividef(1.0f, 1.0f + __expf(-v));
}
__device__ __forceinline__ float fast_tanh(float v) {
    v = fminf(fmaxf(v, -10.0f), 10.0f);
    float e = __expf(2.0f * v);
    return __fdividef(e - 1.0f, e + 1.0f);
}

// Triple 64-dot sharing one h load: weights in u64 register arrays.
__device__ __forceinline__ void dot3(const unsigned long long* __restrict__ wr,
                                     const unsigned long long* __restrict__ wz,
                                     const unsigned long long* __restrict__ wn,
                                     const float* __restrict__ hs,
                                     float& dr, float& dz, float& dn) {
    unsigned long long sr0 = 0ull, sr1 = 0ull;
    unsigned long long sz0 = 0ull, sz1 = 0ull;
    unsigned long long sn0 = 0ull, sn1 = 0ull;
#pragma unroll
    for (int i = 0; i < 32; i += 2) {
        ulonglong2 h2 = *(const ulonglong2*)&hs[2 * i];
        FMA2(sr0, wr[i],     h2.x, sr0);
        FMA2(sr1, wr[i + 1], h2.y, sr1);
        FMA2(sz0, wz[i],     h2.x, sz0);
        FMA2(sz1, wz[i + 1], h2.y, sz1);
        FMA2(sn0, wn[i],     h2.x, sn0);
        FMA2(sn1, wn[i + 1], h2.y, sn1);
    }
    float2 a0 = *(float2*)&sr0, a1 = *(float2*)&sr1;
    dr = (a0.x + a0.y) + (a1.x + a1.y);
    float2 b0 = *(float2*)&sz0, b1 = *(float2*)&sz1;
    dz = (b0.x + b0.y) + (b1.x + b1.y);
    float2 c0 = *(float2*)&sn0, c1 = *(float2*)&sn1;
    dn = (c0.x + c0.y) + (c1.x + c1.y);
}

// ---------------------------------------------------------------------------
// Kernel C v2 (R11 best): fused 2-layer GRU, activation-local (3 dots/thread).
// 192 threads = 3 groups of 64; one block bar + one named bar per superstep.
// ---------------------------------------------------------------------------
__global__ void __launch_bounds__(GG, 1) gru_fused2_kernel(
    const float* __restrict__ Whh0, const float* __restrict__ bih0, const float* __restrict__ bhh0,
    const float* __restrict__ Wih1, const float* __restrict__ Whh1,
    const float* __restrict__ bih1, const float* __restrict__ bhh1,
    float* __restrict__ out)
{
    __shared__ float h0buf[2][HH];
    __shared__ float h1s[HH];
    __shared__ float xg1buf[2][3 * HH];

    const int b   = blockIdx.x;
    const int tid = threadIdx.x;
    const int grp = tid >> 6;        // 0=L0, 1=L1g, 2=L1x
    const int k   = tid & 63;

    const float* wsrc = (grp == 0) ? Whh0 : (grp == 1) ? Whh1 : Wih1;
    unsigned long long wr[32], wz[32], wn[32];
#pragma unroll
    for (int i = 0; i < 32; i++) {
        *(float2*)&wr[i] = *(const float2*)&wsrc[(size_t)k * HH + 2 * i];
        *(float2*)&wz[i] = *(const float2*)&wsrc[(size_t)(64 + k) * HH + 2 * i];
        *(float2*)&wn[i] = *(const float2*)&wsrc[(size_t)(128 + k) * HH + 2 * i];
    }

    float br, bz, bn;
    if (grp == 0)      { br = bhh0[k]; bz = bhh0[64 + k]; bn = bhh0[128 + k]; }
    else if (grp == 1) { br = bhh1[k]; bz = bhh1[64 + k]; bn = bhh1[128 + k]; }
    else               { br = bih1[k]; bz = bih1[64 + k]; bn = bih1[128 + k]; }

    const float* rptr = g_R + (size_t)b * LL * GG;
    float accr = 0.f, accz = 0.f, accn = 0.f;
    float rvr = 0.f, rvz = 0.f, rvn = 0.f;
    if (grp == 0) {
        accr = bih0[k]; accz = bih0[64 + k]; accn = bih0[128 + k];
        rvr = rptr[k]; rvz = rptr[64 + k]; rvn = rptr[128 + k];
    }

    float ghr = 0.f, ghz = 0.f, ghn = 0.f;

    if (tid < HH) { h0buf[0][tid] = 0.0f; h0buf[1][tid] = 0.0f; h1s[tid] = 0.0f; }
    __syncthreads();

    for (int s = 0; s <= LL + 1; s++) {
        if (grp == 0) {
            if (s < LL) {
                const float* hp = h0buf[(s + 1) & 1];   // h0[s-1]
                float gr, gz, gn;
                dot3(wr, wz, wn, hp, gr, gz, gn);
                accr += rvr; accz += rvz; accn += rvn;
                if (s + 1 < LL) {
                    const float* rn = rptr + (size_t)(s + 1) * GG;
                    rvr = rn[k]; rvz = rn[64 + k]; rvn = rn[128 + k];
                }
                float r = fast_sigm(accr + br + gr);
                float z = fast_sigm(accz + bz + gz);
                float n = fast_tanh(accn + r * (bn + gn));
                h0buf[s & 1][k] = (1.0f - z) * n + z * hp[k];
            }
        } else if (grp == 1) {
            if (s >= 2 && s <= LL + 1) {
                int t2 = s - 2;
                const float* xg = xg1buf[t2 & 1];
                float r = fast_sigm(xg[k] + br + ghr);
                float z = fast_sigm(xg[64 + k] + bz + ghz);
                float n = fast_tanh(xg[128 + k] + r * (bn + ghn));
                float hn2 = (1.0f - z) * n + z * h1s[k];
                h1s[k] = hn2;
                out[((size_t)b * LL + t2) * HH + k] = hn2;
            }
            if (s >= 1) {
                asm volatile("bar.sync 1, 64;" ::: "memory");   // h1 write -> dot read
                if (s <= LL) {
                    dot3(wr, wz, wn, h1s, ghr, ghz, ghn);        // gh1 for step s-1
                }
            }
        } else {
            if (s >= 1 && s <= LL) {
                int t = s - 1;
                const float* hp0 = h0buf[t & 1];
                float xr, xz, xn;
                dot3(wr, wz, wn, hp0, xr, xz, xn);
                float* xg = xg1buf[t & 1];
                xg[k]        = br + xr;
                xg[64 + k]   = bz + xz;
                xg[128 + k]  = bn + xn;
            }
        }
        __syncthreads();
    }
}

// ---------------------------------------------------------------------------
extern "C" void kernel_launch(void* const* d_in, const int* in_sizes, int n_in,
                              void* d_out, int out_size)
{
    const float* x    = (const float*)d_in[0];
    const float* cw1  = (const float*)d_in[1];
    const float* cb1  = (const float*)d_in[2];
    const float* cw2  = (const float*)d_in[3];
    const float* cb2  = (const float*)d_in[4];
    const float* Wih0 = (const float*)d_in[5];
    const float* Whh0 = (const float*)d_in[6];
    const float* bih0 = (const float*)d_in[7];
    const float* bhh0 = (const float*)d_in[8];
    const float* Wih1 = (const float*)d_in[9];
    const float* Whh1 = (const float*)d_in[10];
    const float* bih1 = (const float*)d_in[11];
    const float* bhh1 = (const float*)d_in[12];
    float* out = (float*)d_out;

    cudaFuncSetAttribute(siggemm_bf16_kernel,
                         cudaFuncAttributeMaxDynamicSharedMemorySize, SMEM_TC_BYTES);

    wsplit_kernel<<<(65 * GG * 16 + 255) / 256, 256>>>(Wih0);

    augment_kernel<<<BB, LL>>>(x, cw1, cb1, cw2, cb2);

    dim3 gridB(256, 2);
    siggemm_bf16_kernel<<<gridB, 256, SMEM_TC_BYTES>>>();

    gru_fused2_kernel<<<BB, GG>>>(Whh0, bih0, bhh0,
                                  Wih1, Whh1, bih1, bhh1, out);
}

// round 16
// speedup vs baseline: 1.2356x; 1.0253x over previous
#include <cuda_runtime.h>
#include <cuda_bf16.h>
#include <math.h>
#include <stdint.h>

#define BB 64
#define LL 256
#define DIN 55
#define AH 32
#define AC 8
#define CC 64
#define GG 192
#define HH 64
#define SIGW 4160   // CC + CC*CC = 65 * 64

// Scratch (device globals — no runtime allocation allowed)
__device__ float g_P[(size_t)BB * CC * LL];          // p in [b][c][t] layout, 4 MB
__device__ float g_R[(size_t)BB * LL * GG];          // per-step projection increments, 12.6 MB
__device__ uint32_t g_Wsp[(size_t)65 * GG * 64];     // W pre-split bf16 hi/lo half2, 3.2 MB

// ---------------------------------------------------------------------------
// bf16 helpers
// ---------------------------------------------------------------------------
__device__ __forceinline__ float bf_hi(float x) {
    return __bfloat162float(__float2bfloat16_rn(x));
}
__device__ __forceinline__ uint32_t bfpack(float x, float y) {
    __nv_bfloat162 t = __floats2bfloat162_rn(x, y);   // .x = x (low 16 bits)
    return *reinterpret_cast<uint32_t*>(&t);
}

// ---------------------------------------------------------------------------
// Kernel W: pre-split Wih0 into bf16 hi/lo, chunk-major, interleaved layout.
// ---------------------------------------------------------------------------
__global__ void __launch_bounds__(256) wsplit_kernel(const float* __restrict__ Wih0)
{
    int idx = blockIdx.x * 256 + threadIdx.x;       // 65*192*16 quads
    if (idx >= 65 * GG * 16) return;
    int q = idx & 15;
    int g = (idx >> 4) % GG;
    int m = (idx >> 4) / GG;
    float4 w = *(const float4*)(Wih0 + (size_t)g * SIGW + 64 * m + 4 * q);
    float hx = bf_hi(w.x), hy = bf_hi(w.y), hz = bf_hi(w.z), hw = bf_hi(w.w);
    uint32_t* o = g_Wsp + ((size_t)(m * GG + g) * 64) + 4 * q;
    o[0] = bfpack(hx, hy);
    o[1] = bfpack(w.x - hx, w.y - hy);
    o[2] = bfpack(hz, hw);
    o[3] = bfpack(w.z - hz, w.w - hw);
}

// ---------------------------------------------------------------------------
// Kernel A: Augment. p = concat(x, time, relu(x W1^T + b1) W2^T + b2)
// ---------------------------------------------------------------------------
__global__ void __launch_bounds__(LL) augment_kernel(
    const float* __restrict__ x,
    const float* __restrict__ w1, const float* __restrict__ b1,
    const float* __restrict__ w2, const float* __restrict__ b2)
{
    __shared__ float w1s[AH * DIN];
    __shared__ float w2s[AC * AH];
    __shared__ float b1s[AH];
    __shared__ float b2s[AC];

    int b = blockIdx.x;
    int t = threadIdx.x;

    for (int i = threadIdx.x; i < AH * DIN; i += blockDim.x) w1s[i] = w1[i];
    for (int i = threadIdx.x; i < AC * AH; i += blockDim.x)  w2s[i] = w2[i];
    if (threadIdx.x < AH) b1s[threadIdx.x] = b1[threadIdx.x];
    if (threadIdx.x < AC) b2s[threadIdx.x] = b2[threadIdx.x];
    __syncthreads();

    float xv[DIN];
    const float* xp = x + ((size_t)b * LL + t) * DIN;
#pragma unroll
    for (int c = 0; c < DIN; c++) xv[c] = xp[c];

    float hb[AH];
#pragma unroll
    for (int h = 0; h < AH; h++) {
        float acc = b1s[h];
#pragma unroll
        for (int c = 0; c < DIN; c++) acc += w1s[h * DIN + c] * xv[c];
        hb[h] = fmaxf(acc, 0.0f);
    }

    float* Pp = g_P + (size_t)b * CC * LL + t;   // [b][c][t]: stride LL per channel
#pragma unroll
    for (int c = 0; c < DIN; c++) Pp[(size_t)c * LL] = xv[c];
    Pp[(size_t)DIN * LL] = (float)t / (float)(LL - 1);
#pragma unroll
    for (int a = 0; a < AC; a++) {
        float acc = b2s[a];
#pragma unroll
        for (int h = 0; h < AH; h++) acc += w2s[a * AH + h] * hb[h];
        Pp[(size_t)(DIN + 1 + a) * LL] = acc;
    }
}

// ---------------------------------------------------------------------------
// MMA / cp.async helpers
// ---------------------------------------------------------------------------
#define MMA_BF16(c0, c1, c2, c3, a0, a1, a2, a3, b0, b1)                       \
    asm volatile(                                                              \
        "mma.sync.aligned.m16n8k16.row.col.f32.bf16.bf16.f32 "                 \
        "{%0,%1,%2,%3}, {%4,%5,%6,%7}, {%8,%9}, {%0,%1,%2,%3};"                \
        : "+f"(c0), "+f"(c1), "+f"(c2), "+f"(c3)                               \
        : "r"(a0), "r"(a1), "r"(a2), "r"(a3), "r"(b0), "r"(b1))

#define FMA2(d, a, b, c) \
    asm("fma.rn.f32x2 %0, %1, %2, %3;" : "=l"(d) : "l"(a), "l"(b), "l"(c))

__device__ __forceinline__ void cp_async16(uint32_t dst_smem, const void* src) {
    asm volatile("cp.async.cg.shared.global [%0], [%1], 16;"
                 :: "r"(dst_smem), "l"(src));
}
#define CP_COMMIT() asm volatile("cp.async.commit_group;")
#define CP_WAIT0()  asm volatile("cp.async.wait_group 0;" ::: "memory")

// ---------------------------------------------------------------------------
// Kernel B v5 (bf16 split TC, double-buffered W, 2 blocks/SM, 2M x 4N tiling):
//   R[p,g] = sum_m scale_m[p] * (D W_m^T)[p,g],  scale_0 = 1, scale_m = a_{m-1}
// 8 warps as 2 M-warps x 4 N-warps (32 rows x 24 gates per warp).
// Each B fragment pair feeds 6 MMAs (2 mf x 3 split products) -> B-LDS traffic
// halved vs 4Mx2N. nf-outer/ks-inner loop keeps live Y at 8 regs.
// ---------------------------------------------------------------------------
#define PADH 36
#define GT 96
#define WROW 72
#define WBUF_WORDS (GT * WROW)               // 6912 words
#define SM_DH_OFF  (64 * 68)                 // after a_s
#define SM_DL_OFF  (SM_DH_OFF + 64 * PADH)
#define SM_W_OFF   (SM_DL_OFF + 64 * PADH)   // 8960 words
#define SMEM_TC_WORDS (SM_W_OFF + 2 * WBUF_WORDS)
#define SMEM_TC_BYTES (SMEM_TC_WORDS * 4)    // 91136 B

__global__ void __launch_bounds__(256, 2) siggemm_bf16_kernel()
{
    extern __shared__ uint32_t smw[];
    float*    a_s  = (float*)smw;
    uint32_t* Dh2  = smw + SM_DH_OFF;
    uint32_t* Dl2  = smw + SM_DL_OFF;
    uint32_t* Wbuf = smw + SM_W_OFF;

    const uint32_t sbase = (uint32_t)__cvta_generic_to_shared(smw);

    const int ptile = blockIdx.x;
    const int gbase = blockIdx.y * GT;
    const int b  = ptile >> 2;
    const int t0 = (ptile & 3) * 64;
    const int tid  = threadIdx.x;
    const int warp = tid >> 5;
    const int lane = tid & 31;
    const int warpM = warp & 1;              // rows 32*warpM..+31
    const int warpN = warp >> 1;             // gates 24*warpN..+23
    const int lq = lane >> 2;
    const int lr = lane & 3;

    // affine cp.async slots: k=0..5, gate gg0+16k, quad qq (const)
    const int gg0 = tid >> 4;
    const int qq  = tid & 15;
    const uint32_t cp_dst0 = sbase + (SM_W_OFF + gg0 * WROW + 4 * qq) * 4;
    const size_t   cp_src0 = (size_t)(gbase + gg0) * 64 + 4 * qq;

    // ---- issue chunk 0 into buf0 (overlaps a/D staging)
    {
#pragma unroll
        for (int k = 0; k < 6; k++)
            cp_async16(cp_dst0 + (uint32_t)(16 * WROW * 4) * k,
                       g_Wsp + cp_src0 + 1024 * k);
        CP_COMMIT();
    }

    // ---- stage a (fp32) and D (bf16 hi/lo half2 pairs)
    {
        const float* Pb = g_P + (size_t)b * CC * LL;
        for (int idx = tid; idx < 64 * 32; idx += 256) {
            int j2 = idx >> 6;
            int p  = idx & 63;
            int t  = t0 + p;
            const float* Pc0 = Pb + (size_t)(2 * j2) * LL;
            const float* Pc1 = Pc0 + LL;
            float c0 = Pc0[t], p0 = (t == 0) ? 0.0f : Pc0[t - 1];
            float c1 = Pc1[t], p1 = (t == 0) ? 0.0f : Pc1[t - 1];
            float d0 = c0 - p0, d1 = c1 - p1;
            a_s[(2 * j2) * 68 + p]     = 0.5f * (c0 + p0);
            a_s[(2 * j2 + 1) * 68 + p] = 0.5f * (c1 + p1);
            float h0 = bf_hi(d0), h1 = bf_hi(d1);
            Dh2[p * PADH + j2] = bfpack(h0, h1);
            Dl2[p * PADH + j2] = bfpack(d0 - h0, d1 - h1);
        }
    }
    __syncthreads();

    // ---- chunk-invariant A fragments (2 mf x 16 rows per warp)
    uint32_t Ah[2][4][4], Al[2][4][4];
#pragma unroll
    for (int mf = 0; mf < 2; mf++) {
        int r0 = (warpM * 32 + mf * 16 + lq) * PADH;
        int r1 = (warpM * 32 + mf * 16 + 8 + lq) * PADH;
#pragma unroll
        for (int ks = 0; ks < 4; ks++) {
            int c0 = 8 * ks + lr, c1 = 8 * ks + 4 + lr;
            Ah[mf][ks][0] = Dh2[r0 + c0];
            Ah[mf][ks][1] = Dh2[r1 + c0];
            Ah[mf][ks][2] = Dh2[r0 + c1];
            Ah[mf][ks][3] = Dh2[r1 + c1];
            Al[mf][ks][0] = Dl2[r0 + c0];
            Al[mf][ks][1] = Dl2[r1 + c0];
            Al[mf][ks][2] = Dl2[r0 + c1];
            Al[mf][ks][3] = Dl2[r1 + c1];
        }
    }

    float R[2][3][4];
#pragma unroll
    for (int mf = 0; mf < 2; mf++)
#pragma unroll
        for (int nf = 0; nf < 3; nf++)
#pragma unroll
            for (int q = 0; q < 4; q++) R[mf][nf][q] = 0.0f;

    for (int c = 0; c < 65; c++) {
        CP_WAIT0();                          // chunk c landed
        __syncthreads();                     // all warps done with buf (c-1)&1

        // issue chunk c+1 into the other buffer
        if (c + 1 < 65) {
            uint32_t dstb = cp_dst0 + (uint32_t)(((c + 1) & 1) * WBUF_WORDS) * 4;
            const uint32_t* srcn = g_Wsp + (size_t)(c + 1) * GG * 64 + cp_src0;
#pragma unroll
            for (int k = 0; k < 6; k++)
                cp_async16(dstb + (uint32_t)(16 * WROW * 4) * k, srcn + 1024 * k);
        }
        CP_COMMIT();

        const uint32_t* WB = Wbuf + (c & 1) * WBUF_WORDS;

        float av0 = 1.0f, av1 = 1.0f, av2 = 1.0f, av3 = 1.0f;
        if (c > 0) {
            int r0 = warpM * 32 + lq;
            av0 = a_s[(c - 1) * 68 + r0];        // mf=0 rows
            av1 = a_s[(c - 1) * 68 + r0 + 8];
            av2 = a_s[(c - 1) * 68 + r0 + 16];   // mf=1 rows
            av3 = a_s[(c - 1) * 68 + r0 + 24];
        }

        // nf outer, ks inner: live Y = 8 regs; each B pair feeds 6 MMAs.
#pragma unroll
        for (int nf = 0; nf < 3; nf++) {
            float Y[2][4];
#pragma unroll
            for (int mf = 0; mf < 2; mf++)
#pragma unroll
                for (int q = 0; q < 4; q++) Y[mf][q] = 0.0f;

            const int n0 = (warpN * 24 + nf * 8 + lq) * WROW;
#pragma unroll
            for (int ks = 0; ks < 4; ks++) {
                uint2 p0 = *(const uint2*)&WB[n0 + 2 * (8 * ks + lr)];
                uint2 p1 = *(const uint2*)&WB[n0 + 2 * (8 * ks + 4 + lr)];
#pragma unroll
                for (int mf = 0; mf < 2; mf++) {
                    MMA_BF16(Y[mf][0], Y[mf][1], Y[mf][2], Y[mf][3],
                             Ah[mf][ks][0], Ah[mf][ks][1], Ah[mf][ks][2], Ah[mf][ks][3],
                             p0.x, p1.x);
                    MMA_BF16(Y[mf][0], Y[mf][1], Y[mf][2], Y[mf][3],
                             Al[mf][ks][0], Al[mf][ks][1], Al[mf][ks][2], Al[mf][ks][3],
                             p0.x, p1.x);
                    MMA_BF16(Y[mf][0], Y[mf][1], Y[mf][2], Y[mf][3],
                             Ah[mf][ks][0], Ah[mf][ks][1], Ah[mf][ks][2], Ah[mf][ks][3],
                             p0.y, p1.y);
                }
            }

            R[0][nf][0] = fmaf(av0, Y[0][0], R[0][nf][0]);
            R[0][nf][1] = fmaf(av0, Y[0][1], R[0][nf][1]);
            R[0][nf][2] = fmaf(av1, Y[0][2], R[0][nf][2]);
            R[0][nf][3] = fmaf(av1, Y[0][3], R[0][nf][3]);
            R[1][nf][0] = fmaf(av2, Y[1][0], R[1][nf][0]);
            R[1][nf][1] = fmaf(av2, Y[1][1], R[1][nf][1]);
            R[1][nf][2] = fmaf(av3, Y[1][2], R[1][nf][2]);
            R[1][nf][3] = fmaf(av3, Y[1][3], R[1][nf][3]);
        }
    }

    // ---- epilogue
#pragma unroll
    for (int mf = 0; mf < 2; mf++) {
        int trow = t0 + warpM * 32 + mf * 16 + lq;
#pragma unroll
        for (int nf = 0; nf < 3; nf++) {
            int g = gbase + warpN * 24 + nf * 8 + 2 * lr;
            float* rp0 = g_R + ((size_t)b * LL + trow) * GG + g;
            float* rp1 = g_R + ((size_t)b * LL + trow + 8) * GG + g;
            *(float2*)rp0 = make_float2(R[mf][nf][0], R[mf][nf][1]);
            *(float2*)rp1 = make_float2(R[mf][nf][2], R[mf][nf][3]);
        }
    }
}

// ---------------------------------------------------------------------------
// Fast activations
// ---------------------------------------------------------------------------
__device__ __forceinline__ float fast_sigm(float v) {
    return __fdividef(1.0f, 1.0f + __expf(-v));
}
__device__ __forceinline__ float fast_tanh(float v) {
    v = fminf(fmaxf(v, -10.0f), 10.0f);
    float e = __expf(2.0f * v);
    return __fdividef(e - 1.0f, e + 1.0f);
}

// Triple 64-dot sharing one h load: weights in u64 register arrays.
__device__ __forceinline__ void dot3(const unsigned long long* __restrict__ wr,
                                     const unsigned long long* __restrict__ wz,
                                     const unsigned long long* __restrict__ wn,
                                     const float* __restrict__ hs,
                                     float& dr, float& dz, float& dn) {
    unsigned long long sr0 = 0ull, sr1 = 0ull;
    unsigned long long sz0 = 0ull, sz1 = 0ull;
    unsigned long long sn0 = 0ull, sn1 = 0ull;
#pragma unroll
    for (int i = 0; i < 32; i += 2) {
        ulonglong2 h2 = *(const ulonglong2*)&hs[2 * i];
        FMA2(sr0, wr[i],     h2.x, sr0);
        FMA2(sr1, wr[i + 1], h2.y, sr1);
        FMA2(sz0, wz[i],     h2.x, sz0);
        FMA2(sz1, wz[i + 1], h2.y, sz1);
        FMA2(sn0, wn[i],     h2.x, sn0);
        FMA2(sn1, wn[i + 1], h2.y, sn1);
    }
    float2 a0 = *(float2*)&sr0, a1 = *(float2*)&sr1;
    dr = (a0.x + a0.y) + (a1.x + a1.y);
    float2 b0 = *(float2*)&sz0, b1 = *(float2*)&sz1;
    dz = (b0.x + b0.y) + (b1.x + b1.y);
    float2 c0 = *(float2*)&sn0, c1 = *(float2*)&sn1;
    dn = (c0.x + c0.y) + (c1.x + c1.y);
}

// ---------------------------------------------------------------------------
// Kernel C (R11 best): fused 2-layer GRU, activation-local (3 dots/thread).
// 192 threads = 3 groups of 64; one block bar + one named bar per superstep.
// ---------------------------------------------------------------------------
__global__ void __launch_bounds__(GG, 1) gru_fused2_kernel(
    const float* __restrict__ Whh0, const float* __restrict__ bih0, const float* __restrict__ bhh0,
    const float* __restrict__ Wih1, const float* __restrict__ Whh1,
    const float* __restrict__ bih1, const float* __restrict__ bhh1,
    float* __restrict__ out)
{
    __shared__ float h0buf[2][HH];
    __shared__ float h1s[HH];
    __shared__ float xg1buf[2][3 * HH];

    const int b   = blockIdx.x;
    const int tid = threadIdx.x;
    const int grp = tid >> 6;        // 0=L0, 1=L1g, 2=L1x
    const int k   = tid & 63;

    const float* wsrc = (grp == 0) ? Whh0 : (grp == 1) ? Whh1 : Wih1;
    unsigned long long wr[32], wz[32], wn[32];
#pragma unroll
    for (int i = 0; i < 32; i++) {
        *(float2*)&wr[i] = *(const float2*)&wsrc[(size_t)k * HH + 2 * i];
        *(float2*)&wz[i] = *(const float2*)&wsrc[(size_t)(64 + k) * HH + 2 * i];
        *(float2*)&wn[i] = *(const float2*)&wsrc[(size_t)(128 + k) * HH + 2 * i];
    }

    float br, bz, bn;
    if (grp == 0)      { br = bhh0[k]; bz = bhh0[64 + k]; bn = bhh0[128 + k]; }
    else if (grp == 1) { br = bhh1[k]; bz = bhh1[64 + k]; bn = bhh1[128 + k]; }
    else               { br = bih1[k]; bz = bih1[64 + k]; bn = bih1[128 + k]; }

    const float* rptr = g_R + (size_t)b * LL * GG;
    float accr = 0.f, accz = 0.f, accn = 0.f;
    float rvr = 0.f, rvz = 0.f, rvn = 0.f;
    if (grp == 0) {
        accr = bih0[k]; accz = bih0[64 + k]; accn = bih0[128 + k];
        rvr = rptr[k]; rvz = rptr[64 + k]; rvn = rptr[128 + k];
    }

    float ghr = 0.f, ghz = 0.f, ghn = 0.f;

    if (tid < HH) { h0buf[0][tid] = 0.0f; h0buf[1][tid] = 0.0f; h1s[tid] = 0.0f; }
    __syncthreads();

    for (int s = 0; s <= LL + 1; s++) {
        if (grp == 0) {
            if (s < LL) {
                const float* hp = h0buf[(s + 1) & 1];   // h0[s-1]
                float gr, gz, gn;
                dot3(wr, wz, wn, hp, gr, gz, gn);
                accr += rvr; accz += rvz; accn += rvn;
                if (s + 1 < LL) {
                    const float* rn = rptr + (size_t)(s + 1) * GG;
                    rvr = rn[k]; rvz = rn[64 + k]; rvn = rn[128 + k];
                }
                float r = fast_sigm(accr + br + gr);
                float z = fast_sigm(accz + bz + gz);
                float n = fast_tanh(accn + r * (bn + gn));
                h0buf[s & 1][k] = (1.0f - z) * n + z * hp[k];
            }
        } else if (grp == 1) {
            if (s >= 2 && s <= LL + 1) {
                int t2 = s - 2;
                const float* xg = xg1buf[t2 & 1];
                float r = fast_sigm(xg[k] + br + ghr);
                float z = fast_sigm(xg[64 + k] + bz + ghz);
                float n = fast_tanh(xg[128 + k] + r * (bn + ghn));
                float hn2 = (1.0f - z) * n + z * h1s[k];
                h1s[k] = hn2;
                out[((size_t)b * LL + t2) * HH + k] = hn2;
            }
            if (s >= 1) {
                asm volatile("bar.sync 1, 64;" ::: "memory");   // h1 write -> dot read
                if (s <= LL) {
                    dot3(wr, wz, wn, h1s, ghr, ghz, ghn);        // gh1 for step s-1
                }
            }
        } else {
            if (s >= 1 && s <= LL) {
                int t = s - 1;
                const float* hp0 = h0buf[t & 1];
                float xr, xz, xn;
                dot3(wr, wz, wn, hp0, xr, xz, xn);
                float* xg = xg1buf[t & 1];
                xg[k]        = br + xr;
                xg[64 + k]   = bz + xz;
                xg[128 + k]  = bn + xn;
            }
        }
        __syncthreads();
    }
}

// ---------------------------------------------------------------------------
extern "C" void kernel_launch(void* const* d_in, const int* in_sizes, int n_in,
                              void* d_out, int out_size)
{
    const float* x    = (const float*)d_in[0];
    const float* cw1  = (const float*)d_in[1];
    const float* cb1  = (const float*)d_in[2];
    const float* cw2  = (const float*)d_in[3];
    const float* cb2  = (const float*)d_in[4];
    const float* Wih0 = (const float*)d_in[5];
    const float* Whh0 = (const float*)d_in[6];
    const float* bih0 = (const float*)d_in[7];
    const float* bhh0 = (const float*)d_in[8];
    const float* Wih1 = (const float*)d_in[9];
    const float* Whh1 = (const float*)d_in[10];
    const float* bih1 = (const float*)d_in[11];
    const float* bhh1 = (const float*)d_in[12];
    float* out = (float*)d_out;

    cudaFuncSetAttribute(siggemm_bf16_kernel,
                         cudaFuncAttributeMaxDynamicSharedMemorySize, SMEM_TC_BYTES);

    wsplit_kernel<<<(65 * GG * 16 + 255) / 256, 256>>>(Wih0);

    augment_kernel<<<BB, LL>>>(x, cw1, cb1, cw2, cb2);

    dim3 gridB(256, 2);
    siggemm_bf16_kernel<<<gridB, 256, SMEM_TC_BYTES>>>();

    gru_fused2_kernel<<<BB, GG>>>(Whh0, bih0, bhh0,
                                  Wih1, Whh1, bih1, bhh1, out);
}